// round 1
// baseline (speedup 1.0000x reference)
#include <cuda_runtime.h>
#include <math.h>

#define NN 50000
#define EE 800000
#define DD 96
#define CC 40
#define NITE 8
#define SMOOTH 0.5f

// ---------------- scratch (device globals; no allocation allowed) ------------
__device__ float g_h[NN * DD];        // node features, updated in place
__device__ float g_support[NN * DD];  // h @ W_gc
__device__ int   g_count[NN];         // per-row edge count
__device__ int   g_rowstart[NN + 1];  // CSR offsets
__device__ int   g_fill[NN];          // fill cursors
__device__ int   g_dst[EE];           // CSR: source column per edge
__device__ float g_val[EE];           // CSR: edge value

// ---------------- init: h = x, zero counts ----------------------------------
__global__ void init_kernel(const float* __restrict__ x) {
    int i = blockIdx.x * blockDim.x + threadIdx.x;
    if (i < NN * DD) g_h[i] = x[i];
    if (i < NN) g_count[i] = 0;
}

// ---------------- CSR build --------------------------------------------------
__global__ void hist_kernel(const int* __restrict__ erow) {
    int e = blockIdx.x * blockDim.x + threadIdx.x;
    if (e < EE) atomicAdd(&g_count[erow[e]], 1);
}

// Single-block scan over NN counts -> rowstart (exclusive), fill cursors.
__global__ void scan_kernel() {
    __shared__ int part[1024];
    const int CH = (NN + 1023) / 1024;
    int t = threadIdx.x;
    int begin = t * CH;
    int end = begin + CH; if (end > NN) end = NN;
    int s = 0;
    for (int i = begin; i < end; ++i) s += g_count[i];
    part[t] = s;
    __syncthreads();
    // inclusive Hillis-Steele scan
    for (int off = 1; off < 1024; off <<= 1) {
        int v = (t >= off) ? part[t - off] : 0;
        __syncthreads();
        part[t] += v;
        __syncthreads();
    }
    int running = (t == 0) ? 0 : part[t - 1];
    for (int i = begin; i < end; ++i) {
        g_rowstart[i] = running;
        g_fill[i] = running;
        running += g_count[i];
    }
    if (t == 1023) g_rowstart[NN] = running;  // == EE
}

__global__ void fill_kernel(const int* __restrict__ erow,
                            const int* __restrict__ ecol,
                            const float* __restrict__ ev) {
    int e = blockIdx.x * blockDim.x + threadIdx.x;
    if (e < EE) {
        int r = erow[e];
        int p = atomicAdd(&g_fill[r], 1);
        g_dst[p] = ecol[e];
        g_val[p] = ev[e];
    }
}

// ---------------- GEMM: support = h @ W_gc  (NNxDD @ DDxDD) ------------------
// 256 threads (8 warps), 64 rows/block. Each thread: 8 rows x 3 cols.
// W resident in smem; h rows staged in smem; broadcast reads within warp.
__global__ void __launch_bounds__(256) gemm_kernel(const float* __restrict__ W) {
    extern __shared__ float smem[];
    float* Ws = smem;             // DD*DD
    float* Hs = smem + DD * DD;   // 64*DD
    int lane = threadIdx.x;       // 0..31
    int wy = threadIdx.y;         // 0..7
    int tid = wy * 32 + lane;
    int row0 = blockIdx.x * 64;

    for (int i = tid; i < DD * DD; i += 256) Ws[i] = W[i];
    for (int i = tid; i < 64 * DD; i += 256) {
        int r = row0 + i / DD;
        Hs[i] = (r < NN) ? g_h[r * DD + (i % DD)] : 0.f;
    }
    __syncthreads();

    float acc[8][3];
#pragma unroll
    for (int i = 0; i < 8; ++i) { acc[i][0] = 0.f; acc[i][1] = 0.f; acc[i][2] = 0.f; }

#pragma unroll 2
    for (int k = 0; k < DD; ++k) {
        float w0 = Ws[k * DD + lane];
        float w1 = Ws[k * DD + lane + 32];
        float w2 = Ws[k * DD + lane + 64];
#pragma unroll
        for (int i = 0; i < 8; ++i) {
            float hv = Hs[(wy * 8 + i) * DD + k];  // broadcast within warp
            acc[i][0] += hv * w0;
            acc[i][1] += hv * w1;
            acc[i][2] += hv * w2;
        }
    }

#pragma unroll
    for (int i = 0; i < 8; ++i) {
        int r = row0 + wy * 8 + i;
        if (r < NN) {
            g_support[r * DD + lane]      = acc[i][0];
            g_support[r * DD + lane + 32] = acc[i][1];
            g_support[r * DD + lane + 64] = acc[i][2];
        }
    }
}

// ---------------- aggregation + smooth + ReLU (one warp per row) -------------
__global__ void __launch_bounds__(256) agg_kernel(const float* __restrict__ b) {
    int warp = (blockIdx.x * blockDim.x + threadIdx.x) >> 5;
    int lane = threadIdx.x & 31;
    if (warp >= NN) return;
    int j0 = g_rowstart[warp];
    int j1 = g_rowstart[warp + 1];
    float a0 = 0.f, a1 = 0.f, a2 = 0.f;
#pragma unroll 2
    for (int j = j0; j < j1; ++j) {
        int c = __ldg(&g_dst[j]);
        float v = __ldg(&g_val[j]);
        const float* s = g_support + c * DD;
        a0 += s[lane] * v;
        a1 += s[lane + 32] * v;
        a2 += s[lane + 64] * v;
    }
    int base = warp * DD;
    float h0 = g_h[base + lane];
    float h1 = g_h[base + lane + 32];
    float h2 = g_h[base + lane + 64];
    float r0 = SMOOTH * h0 + (1.f - SMOOTH) * (a0 + b[lane]);
    float r1 = SMOOTH * h1 + (1.f - SMOOTH) * (a1 + b[lane + 32]);
    float r2 = SMOOTH * h2 + (1.f - SMOOTH) * (a2 + b[lane + 64]);
    g_h[base + lane]      = fmaxf(r0, 0.f);
    g_h[base + lane + 32] = fmaxf(r1, 0.f);
    g_h[base + lane + 64] = fmaxf(r2, 0.f);
}

// ---------------- final: logits = h @ W_lin, log_softmax ---------------------
__global__ void __launch_bounds__(256) out_kernel(const float* __restrict__ Wl,
                                                  float* __restrict__ out) {
    __shared__ float Ws[DD * CC];   // 15360 B
    __shared__ float Hs[32 * DD];   // 12288 B
    __shared__ float Ls[32 * CC];   //  5120 B
    int tid = threadIdx.x;
    int row0 = blockIdx.x * 32;

    for (int i = tid; i < DD * CC; i += 256) Ws[i] = Wl[i];
    for (int i = tid; i < 32 * DD; i += 256) {
        int r = row0 + i / DD;
        Hs[i] = (r < NN) ? g_h[r * DD + (i % DD)] : 0.f;
    }
    __syncthreads();

    for (int o = tid; o < 32 * CC; o += 256) {
        int r = o / CC, c = o % CC;
        float a = 0.f;
#pragma unroll 4
        for (int k = 0; k < DD; ++k) a += Hs[r * DD + k] * Ws[k * CC + c];
        Ls[o] = a;
    }
    __syncthreads();

    if (tid < 32) {
        int r = row0 + tid;
        if (r < NN) {
            float m = -1e30f;
#pragma unroll
            for (int c = 0; c < CC; ++c) m = fmaxf(m, Ls[tid * CC + c]);
            float s = 0.f;
#pragma unroll
            for (int c = 0; c < CC; ++c) s += expf(Ls[tid * CC + c] - m);
            float lse = m + logf(s);
#pragma unroll
            for (int c = 0; c < CC; ++c) out[r * CC + c] = Ls[tid * CC + c] - lse;
        }
    }
}

// ---------------- launch ------------------------------------------------------
extern "C" void kernel_launch(void* const* d_in, const int* in_sizes, int n_in,
                              void* d_out, int out_size) {
    (void)in_sizes; (void)n_in; (void)out_size;
    const float* x    = (const float*)d_in[0];
    const int*   erow = (const int*)d_in[1];
    const int*   ecol = (const int*)d_in[2];
    const float* ev   = (const float*)d_in[3];
    const float* Wgc  = (const float*)d_in[4];
    const float* bgc  = (const float*)d_in[5];
    const float* Wlin = (const float*)d_in[6];
    float* out = (float*)d_out;

    const int gemm_smem = (DD * DD + 64 * DD) * (int)sizeof(float);  // 61440 B
    cudaFuncSetAttribute(gemm_kernel, cudaFuncAttributeMaxDynamicSharedMemorySize, gemm_smem);

    init_kernel<<<(NN * DD + 255) / 256, 256>>>(x);
    hist_kernel<<<(EE + 255) / 256, 256>>>(erow);
    scan_kernel<<<1, 1024>>>();
    fill_kernel<<<(EE + 255) / 256, 256>>>(erow, ecol, ev);

    for (int it = 0; it < NITE; ++it) {
        gemm_kernel<<<(NN + 63) / 64, dim3(32, 8), gemm_smem>>>(Wgc);
        agg_kernel<<<(NN * 32 + 255) / 256, 256>>>(bgc);
    }

    out_kernel<<<(NN + 31) / 32, 256>>>(Wlin, out);
}

// round 2
// speedup vs baseline: 1.0797x; 1.0797x over previous
#include <cuda_runtime.h>
#include <math.h>

#define NN 50000
#define EE 800000
#define DD 96
#define CC 40
#define NITE 8
#define SMOOTH 0.5f

// Padded transposed-W row stride (floats). 96 % 32 == 0 would put every lane on
// the same smem bank; 98 keeps LDS.64 phase-pairs conflict-free.
#define WT_STRIDE 98

// ---------------- scratch (device globals; no allocation allowed) ------------
__device__ float g_h[NN * DD];        // node features, updated in place
__device__ float g_support[NN * DD];  // h @ W_gc
__device__ int   g_count[NN];         // per-row edge count
__device__ int   g_rowstart[NN + 1];  // CSR offsets
__device__ int   g_fill[NN];          // fill cursors
__device__ int   g_dst[EE];           // CSR: source column per edge
__device__ float g_val[EE];           // CSR: edge value

// packed f32x2 FMA: d.lo += a.lo*b.lo ; d.hi += a.hi*b.hi  (one FFMA2)
__device__ __forceinline__ void ffma2(unsigned long long& d,
                                      unsigned long long a,
                                      unsigned long long b) {
    asm("fma.rn.f32x2 %0, %1, %2, %0;" : "+l"(d) : "l"(a), "l"(b));
}

// ---------------- init: h = x, zero counts ----------------------------------
__global__ void init_kernel(const float* __restrict__ x) {
    int i = blockIdx.x * blockDim.x + threadIdx.x;
    if (i < NN * DD) g_h[i] = x[i];
    if (i < NN) g_count[i] = 0;
}

// ---------------- CSR build --------------------------------------------------
__global__ void hist_kernel(const int* __restrict__ erow) {
    int e = blockIdx.x * blockDim.x + threadIdx.x;
    if (e < EE) atomicAdd(&g_count[erow[e]], 1);
}

__global__ void scan_kernel() {
    __shared__ int part[1024];
    const int CH = (NN + 1023) / 1024;
    int t = threadIdx.x;
    int begin = t * CH;
    int end = begin + CH; if (end > NN) end = NN;
    int s = 0;
    for (int i = begin; i < end; ++i) s += g_count[i];
    part[t] = s;
    __syncthreads();
    for (int off = 1; off < 1024; off <<= 1) {
        int v = (t >= off) ? part[t - off] : 0;
        __syncthreads();
        part[t] += v;
        __syncthreads();
    }
    int running = (t == 0) ? 0 : part[t - 1];
    for (int i = begin; i < end; ++i) {
        g_rowstart[i] = running;
        g_fill[i] = running;
        running += g_count[i];
    }
    if (t == 1023) g_rowstart[NN] = running;  // == EE
}

__global__ void fill_kernel(const int* __restrict__ erow,
                            const int* __restrict__ ecol,
                            const float* __restrict__ ev) {
    int e = blockIdx.x * blockDim.x + threadIdx.x;
    if (e < EE) {
        int r = erow[e];
        int p = atomicAdd(&g_fill[r], 1);
        g_dst[p] = ecol[e];
        g_val[p] = ev[e];
    }
}

// ---------------- GEMM: support = h @ W_gc  (NNxDD @ DDxDD) ------------------
// 256 threads (8 warps), 64 rows/block, thread = 8 rows x 3 cols.
// Packed f32x2: accumulator .lo = even-k partial, .hi = odd-k partial.
//   a-pair  = (h[r][2k], h[r][2k+1])      one broadcast LDS.64 (Hs row-major)
//   b-pair  = (W[2k][c], W[2k+1][c])      one LDS.64 from transposed padded Ws
__global__ void __launch_bounds__(256) gemm_kernel(const float* __restrict__ W) {
    extern __shared__ float smem[];
    float* WsT = smem;                    // [DD cols][WT_STRIDE] transposed W
    float* Hs  = smem + DD * WT_STRIDE;   // [64][DD]
    int lane = threadIdx.x;               // 0..31
    int wy = threadIdx.y;                 // 0..7
    int tid = wy * 32 + lane;
    int row0 = blockIdx.x * 64;

    for (int i = tid; i < DD * DD; i += 256) {
        int k = i / DD, c = i % DD;
        WsT[c * WT_STRIDE + k] = W[i];
    }
    for (int i = tid; i < 64 * DD; i += 256) {
        int r = row0 + i / DD;
        Hs[i] = (r < NN) ? g_h[r * DD + (i % DD)] : 0.f;
    }
    __syncthreads();

    unsigned long long acc[8][3];
#pragma unroll
    for (int i = 0; i < 8; ++i) { acc[i][0] = 0ull; acc[i][1] = 0ull; acc[i][2] = 0ull; }

    const unsigned long long* w0p = (const unsigned long long*)&WsT[(lane)      * WT_STRIDE];
    const unsigned long long* w1p = (const unsigned long long*)&WsT[(lane + 32) * WT_STRIDE];
    const unsigned long long* w2p = (const unsigned long long*)&WsT[(lane + 64) * WT_STRIDE];

#pragma unroll 4
    for (int kk = 0; kk < DD / 2; ++kk) {
        unsigned long long w0 = w0p[kk];
        unsigned long long w1 = w1p[kk];
        unsigned long long w2 = w2p[kk];
#pragma unroll
        for (int i = 0; i < 8; ++i) {
            unsigned long long hv =
                *(const unsigned long long*)&Hs[(wy * 8 + i) * DD + 2 * kk];  // broadcast
            ffma2(acc[i][0], hv, w0);
            ffma2(acc[i][1], hv, w1);
            ffma2(acc[i][2], hv, w2);
        }
    }

#pragma unroll
    for (int i = 0; i < 8; ++i) {
        int r = row0 + wy * 8 + i;
        if (r < NN) {
            float2 a0 = *(float2*)&acc[i][0];
            float2 a1 = *(float2*)&acc[i][1];
            float2 a2 = *(float2*)&acc[i][2];
            g_support[r * DD + lane]      = a0.x + a0.y;
            g_support[r * DD + lane + 32] = a1.x + a1.y;
            g_support[r * DD + lane + 64] = a2.x + a2.y;
        }
    }
}

// ---------------- aggregation + smooth + ReLU (one warp per row) -------------
__global__ void __launch_bounds__(256) agg_kernel(const float* __restrict__ b) {
    int warp = (blockIdx.x * blockDim.x + threadIdx.x) >> 5;
    int lane = threadIdx.x & 31;
    if (warp >= NN) return;
    int j0 = g_rowstart[warp];
    int j1 = g_rowstart[warp + 1];
    float a0 = 0.f, a1 = 0.f, a2 = 0.f;
#pragma unroll 4
    for (int j = j0; j < j1; ++j) {
        int c = __ldg(&g_dst[j]);
        float v = __ldg(&g_val[j]);
        const float* s = g_support + c * DD;
        a0 += s[lane] * v;
        a1 += s[lane + 32] * v;
        a2 += s[lane + 64] * v;
    }
    int base = warp * DD;
    float h0 = g_h[base + lane];
    float h1 = g_h[base + lane + 32];
    float h2 = g_h[base + lane + 64];
    float r0 = SMOOTH * h0 + (1.f - SMOOTH) * (a0 + b[lane]);
    float r1 = SMOOTH * h1 + (1.f - SMOOTH) * (a1 + b[lane + 32]);
    float r2 = SMOOTH * h2 + (1.f - SMOOTH) * (a2 + b[lane + 64]);
    g_h[base + lane]      = fmaxf(r0, 0.f);
    g_h[base + lane + 32] = fmaxf(r1, 0.f);
    g_h[base + lane + 64] = fmaxf(r2, 0.f);
}

// ---------------- final: logits = h @ W_lin, log_softmax ---------------------
__global__ void __launch_bounds__(256) out_kernel(const float* __restrict__ Wl,
                                                  float* __restrict__ out) {
    __shared__ float Ws[DD * CC];   // 15360 B
    __shared__ float Hs[32 * DD];   // 12288 B
    __shared__ float Ls[32 * CC];   //  5120 B
    int tid = threadIdx.x;
    int row0 = blockIdx.x * 32;

    for (int i = tid; i < DD * CC; i += 256) Ws[i] = Wl[i];
    for (int i = tid; i < 32 * DD; i += 256) {
        int r = row0 + i / DD;
        Hs[i] = (r < NN) ? g_h[r * DD + (i % DD)] : 0.f;
    }
    __syncthreads();

    for (int o = tid; o < 32 * CC; o += 256) {
        int r = o / CC, c = o % CC;
        float a = 0.f;
#pragma unroll 4
        for (int k = 0; k < DD; ++k) a += Hs[r * DD + k] * Ws[k * CC + c];
        Ls[o] = a;
    }
    __syncthreads();

    if (tid < 32) {
        int r = row0 + tid;
        if (r < NN) {
            float m = -1e30f;
#pragma unroll
            for (int c = 0; c < CC; ++c) m = fmaxf(m, Ls[tid * CC + c]);
            float s = 0.f;
#pragma unroll
            for (int c = 0; c < CC; ++c) s += expf(Ls[tid * CC + c] - m);
            float lse = m + logf(s);
#pragma unroll
            for (int c = 0; c < CC; ++c) out[r * CC + c] = Ls[tid * CC + c] - lse;
        }
    }
}

// ---------------- launch ------------------------------------------------------
extern "C" void kernel_launch(void* const* d_in, const int* in_sizes, int n_in,
                              void* d_out, int out_size) {
    (void)in_sizes; (void)n_in; (void)out_size;
    const float* x    = (const float*)d_in[0];
    const int*   erow = (const int*)d_in[1];
    const int*   ecol = (const int*)d_in[2];
    const float* ev   = (const float*)d_in[3];
    const float* Wgc  = (const float*)d_in[4];
    const float* bgc  = (const float*)d_in[5];
    const float* Wlin = (const float*)d_in[6];
    float* out = (float*)d_out;

    const int gemm_smem = (DD * WT_STRIDE + 64 * DD) * (int)sizeof(float);  // 62208 B
    cudaFuncSetAttribute(gemm_kernel, cudaFuncAttributeMaxDynamicSharedMemorySize, gemm_smem);

    init_kernel<<<(NN * DD + 255) / 256, 256>>>(x);
    hist_kernel<<<(EE + 255) / 256, 256>>>(erow);
    scan_kernel<<<1, 1024>>>();
    fill_kernel<<<(EE + 255) / 256, 256>>>(erow, ecol, ev);

    for (int it = 0; it < NITE; ++it) {
        gemm_kernel<<<(NN + 63) / 64, dim3(32, 8), gemm_smem>>>(Wgc);
        agg_kernel<<<(NN * 32 + 255) / 256, 256>>>(bgc);
    }

    out_kernel<<<(NN + 31) / 32, 256>>>(Wlin, out);
}